// round 10
// baseline (speedup 1.0000x reference)
#include <cuda_runtime.h>

// HawkesKT — table-collapsed, MUFU-paced inner loop.
// G[c][e] = (alpha, -clip(beta+1,0,10)/ln5); main kernel computes
//   sum_{i<j} ga * 2^(gb * log2(|ti-tj| + 1e-10))   (1 LG2 + 1 EX2 per pair)

#define NJ  8          // j-columns per CTA
#define RSJ 514        // per-j row stride in float2 units (512 + 2 pad, 16B-aligned rows)

__device__ float2 g_pack[256 * 512];   // [c][e] -> (ga, gb)

__device__ __forceinline__ float fast_ex2(float x) {
    float r;
    asm("ex2.approx.f32 %0, %1;" : "=f"(r) : "f"(x));
    return r;
}

// ---------------- Precompute: dual 512x256x64 GEMM into packed table (256 CTAs) ----------------
__global__ __launch_bounds__(256)
void precompute_kernel(const float* __restrict__ a_inter,    // [512,64]
                       const float* __restrict__ a_concept,  // [256,64]
                       const float* __restrict__ b_inter,    // [512,64]
                       const float* __restrict__ b_concept)  // [256,64]
{
    __shared__ float4 ai[2][16], bi[2][16];   // [e_local][d4]
    const int e0  = blockIdx.x * 2;
    const int tid = threadIdx.x;
    if (tid < 32) {
        ai[tid >> 4][tid & 15] = ((const float4*)a_inter)[(e0 + (tid >> 4)) * 16 + (tid & 15)];
    } else if (tid < 64) {
        int t = tid - 32;
        bi[t >> 4][t & 15] = ((const float4*)b_inter)[(e0 + (t >> 4)) * 16 + (t & 15)];
    }
    __syncthreads();

    const int c = tid;
    float acc_a[2] = {0.f, 0.f};
    float acc_b[2] = {0.f, 0.f};

    #pragma unroll
    for (int d4 = 0; d4 < 16; d4++) {
        float4 av = ((const float4*)a_concept)[c * 16 + d4];
        float4 bv = ((const float4*)b_concept)[c * 16 + d4];
        #pragma unroll
        for (int e = 0; e < 2; e++) {
            float4 u = ai[e][d4];
            float4 w = bi[e][d4];
            acc_a[e] = fmaf(av.x, u.x, fmaf(av.y, u.y, fmaf(av.z, u.z, fmaf(av.w, u.w, acc_a[e]))));
            acc_b[e] = fmaf(bv.x, w.x, fmaf(bv.y, w.y, fmaf(bv.z, w.z, fmaf(bv.w, w.w, acc_b[e]))));
        }
    }
    #pragma unroll
    for (int e = 0; e < 2; e++) {
        float beta = fminf(fmaxf(acc_b[e] + 1.0f, 0.0f), 10.0f);
        g_pack[c * 512 + e0 + e] = make_float2(acc_a[e], -beta * 0.62133497f);  // -beta/ln5
    }
}

// ---------------- Main: causal elementwise sum ----------------
__global__ __launch_bounds__(256)
void hawkes_main(const int* __restrict__ concept_seq,      // [32,1024]
                 const int* __restrict__ question_seq,     // [32,1024]
                 const int* __restrict__ correctness_seq,  // [32,1024]
                 const int* __restrict__ time_seq,         // [32,1024]
                 const float* __restrict__ q_bias,         // [10000]
                 const float* __restrict__ c_bias,         // [256]
                 float* __restrict__ out)                  // [32,1023]
{
    constexpr int SEQ = 1024;
    extern __shared__ float2 sm2[];
    float2* Gs   = sm2;                   // [NJ][RSJ] -> (ga, gb) per (j-lane, e)
    float2* tse  = Gs + NJ * RSJ;         // [<=1024] -> (time, e as int bits)
    float*  jred = (float*)(tse + SEQ);   // [NJ]

    const int b   = blockIdx.y;
    const int j0  = ((int)gridDim.x - 1 - (int)blockIdx.x) * NJ;  // big tiles first
    const int tid = threadIdx.x;
    const int tj  = tid & (NJ - 1);       // 0..7
    const int si  = tid >> 3;             // 0..31
    const int iend = j0 + NJ;

    // Stage (time, e) for the i-range this CTA consumes
    for (int i = tid; i < iend; i += 256) {
        int g = b * SEQ + i;
        int e = concept_seq[g] + (correctness_seq[g] << 8);
        tse[i] = make_float2((float)time_seq[g], __int_as_float(e));
    }
    if (tid < NJ) jred[tid] = 0.0f;

    // Gather packed rows: Gs[jl][e] <- g_pack[c_j][e], straight LDG.128 -> STS.128
    for (int idx = tid; idx < NJ * 256; idx += 256) {
        int jl = idx >> 8;                // 0..7
        int q  = idx & 255;               // float4 index (2 float2 entries)
        int cj = concept_seq[b * SEQ + j0 + jl];
        float4 v = ((const float4*)(g_pack + cj * 512))[q];
        *(float4*)(Gs + jl * RSJ + 2 * q) = v;
    }
    __syncthreads();

    const int    jg    = j0 + tj;
    const float  tjv   = tse[jg].x;
    const float2* Grow = Gs + tj * RSJ;
    float jsum0 = 0.0f, jsum1 = 0.0f;

    // ---- Main region: i in [0, I0), NO causal mask needed (I0 <= j0 <= jg for all lanes) ----
    const int I0 = j0 & ~63;              // multiple of 64
    const float4* tse4 = (const float4*)tse;   // pairs of (t,e)
    const int kend = I0 >> 6;             // iterations; each covers i = 64k+2si, +1

    #pragma unroll 4
    for (int k = 0; k < kend; k++) {
        float4 tp = tse4[k * 32 + si];    // LDS.128: (t0,e0,t1,e1)
        float2 g0 = Grow[__float_as_int(tp.y)];
        float2 g1 = Grow[__float_as_int(tp.w)];
        float lg0 = __log2f(fabsf(tp.x - tjv) + 1e-10f);
        float lg1 = __log2f(fabsf(tp.z - tjv) + 1e-10f);
        jsum0 = fmaf(g0.x, fast_ex2(g0.y * lg0), jsum0);
        jsum1 = fmaf(g1.x, fast_ex2(g1.y * lg1), jsum1);
    }

    // ---- Tail: i in [I0, iend), masked i < jg (<= 72 i's -> <= 3 iterations) ----
    for (int i = I0 + si; i < iend; i += 32) {
        float2 tv = tse[i];
        float2 g  = Grow[__float_as_int(tv.y)];
        float lg  = __log2f(fabsf(tv.x - tjv) + 1e-10f);
        float ex  = fast_ex2(g.y * lg);
        jsum0 += (i < jg) ? g.x * ex : 0.0f;
    }

    // Reduce 32 i-slots -> per-j
    float jsum = jsum0 + jsum1;
    jsum += __shfl_down_sync(0xffffffffu, jsum, 16);
    jsum += __shfl_down_sync(0xffffffffu, jsum, 8);
    if ((tid & 31) < NJ) atomicAdd(&jred[tj], jsum);
    __syncthreads();

    // Epilogue: bias + sigmoid; output drops j=0
    if (tid < NJ) {
        int j = j0 + tid;
        if (j > 0) {
            float x = q_bias[question_seq[b * SEQ + j]]
                    + c_bias[concept_seq[b * SEQ + j]]
                    + jred[tid];
            out[b * (SEQ - 1) + (j - 1)] = 1.0f / (1.0f + __expf(-x));
        }
    }
}

extern "C" void kernel_launch(void* const* d_in, const int* in_sizes, int n_in,
                              void* d_out, int out_size)
{
    (void)in_sizes; (void)n_in; (void)out_size;
    const int*   concept_seq     = (const int*)  d_in[0];
    const int*   question_seq    = (const int*)  d_in[1];
    const int*   correctness_seq = (const int*)  d_in[2];
    const int*   time_seq        = (const int*)  d_in[3];
    const float* a_inter         = (const float*)d_in[4];
    const float* a_concept       = (const float*)d_in[5];
    const float* b_inter         = (const float*)d_in[6];
    const float* b_concept       = (const float*)d_in[7];
    const float* q_bias          = (const float*)d_in[8];
    const float* c_bias          = (const float*)d_in[9];
    float* out = (float*)d_out;

    precompute_kernel<<<256, 256>>>(a_inter, a_concept, b_inter, b_concept);

    const int smem_bytes = (NJ * RSJ + 1024) * (int)sizeof(float2) + NJ * (int)sizeof(float);
    cudaFuncSetAttribute(hawkes_main,
                         cudaFuncAttributeMaxDynamicSharedMemorySize, smem_bytes);
    dim3 grid(1024 / NJ, 32);   // (j-tiles, batches)
    hawkes_main<<<grid, 256, smem_bytes>>>(
        concept_seq, question_seq, correctness_seq, time_seq,
        q_bias, c_bias, out);
}

// round 11
// speedup vs baseline: 1.1558x; 1.1558x over previous
#include <cuda_runtime.h>
#include <cuda_fp16.h>

// HawkesKT — table-collapsed, fp16-packed table, NJ=16.
// Table entry: half2(ga, d) with d = -(beta-1)/ln5.
// Inner: sum_{i<j} ga * 2^((d - 1/ln5) * log2(|ti-tj| + 1e-10))   (1 LG2 + 1 EX2 per pair)

#define NJ  16         // j-columns per CTA
#define RSJ 515        // Gs row stride in half2 units (odd-ish: bank = 3*tj + e, conflict-free)

__device__ __half2 g_pack[256 * 512];   // [c][e] -> (ga, d)

__device__ __forceinline__ float fast_ex2(float x) {
    float r;
    asm("ex2.approx.f32 %0, %1;" : "=f"(r) : "f"(x));
    return r;
}

// ---------------- Precompute: dual 512x256x64 GEMM into packed fp16 table ----------------
__global__ __launch_bounds__(256)
void precompute_kernel(const float* __restrict__ a_inter,    // [512,64]
                       const float* __restrict__ a_concept,  // [256,64]
                       const float* __restrict__ b_inter,    // [512,64]
                       const float* __restrict__ b_concept)  // [256,64]
{
    __shared__ float4 ai[2][16], bi[2][16];   // [e_local][d4]
    const int e0  = blockIdx.x * 2;
    const int tid = threadIdx.x;
    if (tid < 32) {
        ai[tid >> 4][tid & 15] = ((const float4*)a_inter)[(e0 + (tid >> 4)) * 16 + (tid & 15)];
    } else if (tid < 64) {
        int t = tid - 32;
        bi[t >> 4][t & 15] = ((const float4*)b_inter)[(e0 + (t >> 4)) * 16 + (t & 15)];
    }
    __syncthreads();

    const int c = tid;
    float acc_a[2] = {0.f, 0.f};
    float acc_b[2] = {0.f, 0.f};

    #pragma unroll
    for (int d4 = 0; d4 < 16; d4++) {
        float4 av = ((const float4*)a_concept)[c * 16 + d4];
        float4 bv = ((const float4*)b_concept)[c * 16 + d4];
        #pragma unroll
        for (int e = 0; e < 2; e++) {
            float4 u = ai[e][d4];
            float4 w = bi[e][d4];
            acc_a[e] = fmaf(av.x, u.x, fmaf(av.y, u.y, fmaf(av.z, u.z, fmaf(av.w, u.w, acc_a[e]))));
            acc_b[e] = fmaf(bv.x, w.x, fmaf(bv.y, w.y, fmaf(bv.z, w.z, fmaf(bv.w, w.w, acc_b[e]))));
        }
    }
    #pragma unroll
    for (int e = 0; e < 2; e++) {
        float beta = fminf(fmaxf(acc_b[e] + 1.0f, 0.0f), 10.0f);
        float d    = -0.62133497f * (beta - 1.0f);   // delta from beta=1, small -> fp16-safe
        g_pack[c * 512 + e0 + e] = __floats2half2_rn(acc_a[e], d);
    }
}

// ---------------- Main: causal elementwise sum ----------------
__global__ __launch_bounds__(256)
void hawkes_main(const int* __restrict__ concept_seq,      // [32,1024]
                 const int* __restrict__ question_seq,     // [32,1024]
                 const int* __restrict__ correctness_seq,  // [32,1024]
                 const int* __restrict__ time_seq,         // [32,1024]
                 const float* __restrict__ q_bias,         // [10000]
                 const float* __restrict__ c_bias,         // [256]
                 float* __restrict__ out)                  // [32,1023]
{
    constexpr int SEQ = 1024;
    const float C0 = 0.62133497f;                  // 1/ln5

    extern __shared__ unsigned char smraw[];
    __half2* Gs  = (__half2*)smraw;                // [NJ][RSJ]
    float2*  tse = (float2*)(smraw + NJ * RSJ * 4);// [<=1024] (time, e*4 as int bits)
    float*  jred = (float*)(tse + SEQ);            // [NJ]

    const int b   = blockIdx.y;
    const int j0  = ((int)gridDim.x - 1 - (int)blockIdx.x) * NJ;  // big tiles first
    const int tid = threadIdx.x;
    const int tj  = tid & (NJ - 1);                // 0..15
    const int si  = tid >> 4;                      // 0..15
    const int iend = j0 + NJ;

    // Stage (time, e*4) for the i-range this CTA consumes
    for (int i = tid; i < iend; i += 256) {
        int g = b * SEQ + i;
        int e = concept_seq[g] + (correctness_seq[g] << 8);
        tse[i] = make_float2((float)time_seq[g], __int_as_float(e * 4));
    }
    if (tid < NJ) jred[tid] = 0.0f;

    // Gather packed rows: Gs[jl][e] <- g_pack[c_j][e]  (LDG.128 = 4 half2 entries)
    for (int idx = tid; idx < NJ * 128; idx += 256) {
        int jl = idx >> 7;               // 0..15
        int q  = idx & 127;              // uint4 index (4 half2 entries at e=4q)
        int cj = concept_seq[b * SEQ + j0 + jl];
        uint4 v = ((const uint4*)(g_pack + cj * 512))[q];
        __half2* dst = Gs + jl * RSJ + 4 * q;
        dst[0] = *(__half2*)&v.x;  dst[1] = *(__half2*)&v.y;
        dst[2] = *(__half2*)&v.z;  dst[3] = *(__half2*)&v.w;
    }
    __syncthreads();

    const int   jg   = j0 + tj;
    const float tjv  = tse[jg].x;
    const char* Grow = (const char*)(Gs + tj * RSJ);
    float jsum0 = 0.0f, jsum1 = 0.0f;

    // ---- Main region: i in [0, I0), no causal mask (I0 <= j0 <= jg) ----
    const int I0 = j0 & ~31;                        // multiple of 32
    const float4* tse4 = (const float4*)tse;        // pairs of (t, e4)
    const int kend = I0 >> 5;                       // each k covers i = 32k + 2si + {0,1}

    #pragma unroll 4
    for (int k = 0; k < kend; k++) {
        float4 tp = tse4[k * 16 + si];              // LDS.128
        float2 g0 = __half22float2(*(const __half2*)(Grow + __float_as_int(tp.y)));
        float2 g1 = __half22float2(*(const __half2*)(Grow + __float_as_int(tp.w)));
        float lg0 = __log2f(fabsf(tp.x - tjv) + 1e-10f);
        float lg1 = __log2f(fabsf(tp.z - tjv) + 1e-10f);
        float a0  = fmaf(g0.y, lg0, -C0 * lg0);     // (d - C0) * lg
        float a1  = fmaf(g1.y, lg1, -C0 * lg1);
        jsum0 = fmaf(g0.x, fast_ex2(a0), jsum0);
        jsum1 = fmaf(g1.x, fast_ex2(a1), jsum1);
    }

    // ---- Tail: i in [I0, iend), masked i < jg (<= 32 i's -> <= 2 iterations) ----
    for (int i = I0 + si; i < iend; i += 16) {
        float2 tv = tse[i];
        float2 g  = __half22float2(*(const __half2*)(Grow + __float_as_int(tv.y)));
        float lg  = __log2f(fabsf(tv.x - tjv) + 1e-10f);
        float ex  = fast_ex2(fmaf(g.y, lg, -C0 * lg));
        jsum0 += (i < jg) ? g.x * ex : 0.0f;
    }

    // Reduce si slots -> per-j (warp has 2 si-groups of 16 lanes)
    float jsum = jsum0 + jsum1;
    jsum += __shfl_down_sync(0xffffffffu, jsum, 16);
    if ((tid & 31) < NJ) atomicAdd(&jred[tj], jsum);
    __syncthreads();

    // Epilogue: bias + sigmoid; output drops j=0
    if (tid < NJ) {
        int j = j0 + tid;
        if (j > 0) {
            float x = q_bias[question_seq[b * SEQ + j]]
                    + c_bias[concept_seq[b * SEQ + j]]
                    + jred[tid];
            out[b * (SEQ - 1) + (j - 1)] = 1.0f / (1.0f + __expf(-x));
        }
    }
}

extern "C" void kernel_launch(void* const* d_in, const int* in_sizes, int n_in,
                              void* d_out, int out_size)
{
    (void)in_sizes; (void)n_in; (void)out_size;
    const int*   concept_seq     = (const int*)  d_in[0];
    const int*   question_seq    = (const int*)  d_in[1];
    const int*   correctness_seq = (const int*)  d_in[2];
    const int*   time_seq        = (const int*)  d_in[3];
    const float* a_inter         = (const float*)d_in[4];
    const float* a_concept       = (const float*)d_in[5];
    const float* b_inter         = (const float*)d_in[6];
    const float* b_concept       = (const float*)d_in[7];
    const float* q_bias          = (const float*)d_in[8];
    const float* c_bias          = (const float*)d_in[9];
    float* out = (float*)d_out;

    precompute_kernel<<<256, 256>>>(a_inter, a_concept, b_inter, b_concept);

    const int smem_bytes = NJ * RSJ * 4 + 1024 * 8 + NJ * 4;   // ~41.2 KB
    cudaFuncSetAttribute(hawkes_main,
                         cudaFuncAttributeMaxDynamicSharedMemorySize, smem_bytes);
    dim3 grid(1024 / NJ, 32);   // (j-tiles, batches)
    hawkes_main<<<grid, 256, smem_bytes>>>(
        concept_seq, question_seq, correctness_seq, time_seq,
        q_bias, c_bias, out);
}